// round 3
// baseline (speedup 1.0000x reference)
#include <cuda_runtime.h>
#include <cstdint>

#define BB 4
#define CH 1024
#define HH 50
#define WW 50
#define KK 512
#define NPIX (HH*WW)              // 2500
#define GPTS 8                    // grid points per axis (AH+1)

// NHWC-transposed features: [B][H][W][C]  (41 MB device-global scratch)
__device__ __align__(16) float FT[BB * HH * WW * CH];

// ---------------------------------------------------------------------------
// Kernel 1: NCHW -> NHWC transpose (per batch: [C, 2500] -> [2500, C])
// ---------------------------------------------------------------------------
__global__ void transpose_kernel(const float* __restrict__ f) {
    __shared__ float tile[32][33];
    int b  = blockIdx.z;
    int p0 = blockIdx.x * 32;   // pixel index (y*W + x)
    int c0 = blockIdx.y * 32;   // channel
    int tx = threadIdx.x, ty = threadIdx.y;   // 32 x 8

    const float* fb = f + (size_t)b * CH * NPIX;
    #pragma unroll
    for (int i = ty; i < 32; i += 8) {
        int c = c0 + i;
        int p = p0 + tx;
        tile[i][tx] = (p < NPIX) ? fb[(size_t)c * NPIX + p] : 0.0f;
    }
    __syncthreads();
    float* ob = FT + (size_t)b * NPIX * CH;
    #pragma unroll
    for (int i = ty; i < 32; i += 8) {
        int p = p0 + i;
        int c = c0 + tx;
        if (p < NPIX) ob[(size_t)p * CH + c] = tile[tx][i];
    }
}

// ---------------------------------------------------------------------------
// Kernel 2: fused RoIAlign (8x8 bilinear grid) + 2x2 avg pool -> (K,C,7,7)
// One block per roi, 256 threads, 4 channels/thread (float4 taps).
// Streaming row accumulator: pooled[py] = 0.25*(rowsum[py] + rowsum[py+1]);
// only one 7-wide float4 row buffer is kept live.
// ---------------------------------------------------------------------------
__global__ __launch_bounds__(256, 2)
void roi_pool_kernel(const float* __restrict__ rois, float* __restrict__ out) {
    const int k   = blockIdx.x;
    const int tid = threadIdx.x;

    __shared__ __align__(16) float srow[7][CH];     // 28 KB row staging
    __shared__ float s_wx[GPTS], s_wy[GPTS], s_vx[GPTS], s_vy[GPTS];
    __shared__ int   s_x0[GPTS], s_y0[GPTS];
    __shared__ int   s_b;

    if (tid < GPTS) {
        float x1 = __ldg(&rois[k * 5 + 1]) * 0.0625f;
        float y1 = __ldg(&rois[k * 5 + 2]) * 0.0625f;
        float x2 = __ldg(&rois[k * 5 + 3]) * 0.0625f;
        float y2 = __ldg(&rois[k * 5 + 4]) * 0.0625f;
        float bh = fmaxf(y2 - y1, 0.0f) * (1.0f / 7.0f);
        float bw = fmaxf(x2 - x1, 0.0f) * (1.0f / 7.0f);
        float xv = x1 + (float)tid * bw;
        float yv = y1 + (float)tid * bh;
        s_vx[tid] = (xv >= 0.0f && xv < (float)WW) ? 1.0f : 0.0f;
        s_vy[tid] = (yv >= 0.0f && yv < (float)HH) ? 1.0f : 0.0f;
        int x0 = (int)floorf(xv);  x0 = min(max(x0, 0), WW - 2);
        int y0 = (int)floorf(yv);  y0 = min(max(y0, 0), HH - 2);
        s_x0[tid] = x0;  s_y0[tid] = y0;
        s_wx[tid] = xv - (float)x0;
        s_wy[tid] = yv - (float)y0;
        if (tid == 0) s_b = (int)__ldg(&rois[k * 5 + 0]);
    }
    __syncthreads();

    const int c0 = tid * 4;
    const float* bptr = FT + (size_t)s_b * (NPIX * CH) + c0;
    float* outk = out + (size_t)k * (CH * 49);

    // precompute per-gx column byte offsets (registers, reused by all 8 rows)
    int xoff[GPTS];
    float wxr[GPTS], vxr[GPTS];
    #pragma unroll
    for (int gx = 0; gx < GPTS; gx++) {
        xoff[gx] = s_x0[gx] * CH;
        wxr[gx]  = s_wx[gx];
        vxr[gx]  = s_vx[gx];
    }

    float4 prev[7];   // rowsum of previous grid row

    #pragma unroll
    for (int gy = 0; gy < GPTS; gy++) {
        const float wy = s_wy[gy];
        const float vy = s_vy[gy];
        const float* r0 = bptr + (size_t)s_y0[gy] * (WW * CH);
        const float* r1 = r0 + WW * CH;

        float4 rh[7];
        float4 cprev;
        #pragma unroll
        for (int gx = 0; gx < GPTS; gx++) {
            const float wx = wxr[gx];
            const float sc = vy * vxr[gx];

            const float4 v00 = *(const float4*)(r0 + xoff[gx]);
            const float4 v01 = *(const float4*)(r0 + xoff[gx] + CH);
            const float4 v10 = *(const float4*)(r1 + xoff[gx]);
            const float4 v11 = *(const float4*)(r1 + xoff[gx] + CH);

            // fold valid-mask scale into the 4 bilinear weights
            const float w00 = (1.0f - wy) * (1.0f - wx) * sc;
            const float w01 = (1.0f - wy) * wx * sc;
            const float w10 = wy * (1.0f - wx) * sc;
            const float w11 = wy * wx * sc;

            float4 cur;
            cur.x = v00.x*w00 + v01.x*w01 + v10.x*w10 + v11.x*w11;
            cur.y = v00.y*w00 + v01.y*w01 + v10.y*w10 + v11.y*w11;
            cur.z = v00.z*w00 + v01.z*w01 + v10.z*w10 + v11.z*w11;
            cur.w = v00.w*w00 + v01.w*w01 + v10.w*w10 + v11.w*w11;

            if (gx > 0) {
                rh[gx-1].x = cprev.x + cur.x;
                rh[gx-1].y = cprev.y + cur.y;
                rh[gx-1].z = cprev.z + cur.z;
                rh[gx-1].w = cprev.w + cur.w;
            }
            cprev = cur;
        }

        if (gy > 0) {
            // pooled row (gy-1): 0.25*(prev + rh) -> stage in smem
            #pragma unroll
            for (int px = 0; px < 7; px++) {
                float4 o;
                o.x = 0.25f * (prev[px].x + rh[px].x);
                o.y = 0.25f * (prev[px].y + rh[px].y);
                o.z = 0.25f * (prev[px].z + rh[px].z);
                o.w = 0.25f * (prev[px].w + rh[px].w);
                *(float4*)(&srow[px][c0]) = o;
            }
            __syncthreads();

            // drain: 7168 floats, linear index map keeps warp stores within
            // consecutive 28B channel runs (good sector efficiency)
            float* rowout = outk + (gy - 1) * 7;
            #pragma unroll 4
            for (int i = tid; i < 7 * CH; i += 256) {
                int c  = i / 7;
                int px = i - c * 7;
                rowout[c * 49 + px] = srow[px][c];
            }
            __syncthreads();
        }

        #pragma unroll
        for (int px = 0; px < 7; px++) prev[px] = rh[px];
    }
}

// ---------------------------------------------------------------------------
extern "C" void kernel_launch(void* const* d_in, const int* in_sizes, int n_in,
                              void* d_out, int out_size) {
    const float* features = (const float*)d_in[0];
    const float* rois     = (const float*)d_in[1];
    float* out            = (float*)d_out;

    dim3 tgrid((NPIX + 31) / 32, CH / 32, BB);   // (79, 32, 4)
    transpose_kernel<<<tgrid, dim3(32, 8)>>>(features);
    roi_pool_kernel<<<KK, 256>>>(rois, out);
}

// round 4
// speedup vs baseline: 1.8407x; 1.8407x over previous
#include <cuda_runtime.h>
#include <cstdint>

#define BB 4
#define CH 1024
#define HH 50
#define WW 50
#define KK 512
#define NPIX (HH*WW)              // 2500
#define GPTS 8                    // grid points per axis

// NHWC-transposed features: [B][H][W][C]  (41 MB device-global scratch)
__device__ __align__(16) float FT[BB * HH * WW * CH];

// ---------------------------------------------------------------------------
// Kernel 1: NCHW -> NHWC transpose, float4 both sides.
// Tile: 32 channels x 128 pixels. Block 256 threads.
// tile stride 133 => conflict-free smem in both phases.
// ---------------------------------------------------------------------------
__global__ __launch_bounds__(256)
void transpose_kernel(const float* __restrict__ f) {
    __shared__ __align__(16) float tile[32][133];
    const int b  = blockIdx.z;
    const int p0 = blockIdx.x * 128;   // pixel base (multiple of 128)
    const int c0 = blockIdx.y * 32;    // channel base
    const int t  = threadIdx.x;

    const float* fb = f + (size_t)b * CH * NPIX + (size_t)c0 * NPIX;

    // load: 1024 float4 slots (32 c-rows x 32 float4s)
    #pragma unroll
    for (int j = 0; j < 4; j++) {
        int idx = t + j * 256;
        int c = idx >> 5;            // 0..31
        int q = idx & 31;            // float4 column
        int p = p0 + 4 * q;
        float4 v = make_float4(0.f, 0.f, 0.f, 0.f);
        if (p < NPIX)                // NPIX % 4 == 0 -> all-or-nothing
            v = *(const float4*)(fb + (size_t)c * NPIX + p);
        tile[c][4 * q + 0] = v.x;
        tile[c][4 * q + 1] = v.y;
        tile[c][4 * q + 2] = v.z;
        tile[c][4 * q + 3] = v.w;
    }
    __syncthreads();

    float* ob = FT + (size_t)b * NPIX * CH + c0;
    // store: 128 pixels x 8 channel-groups of 4
    #pragma unroll
    for (int j = 0; j < 4; j++) {
        int idx = t + j * 256;
        int p = idx >> 3;            // 0..127
        int g = idx & 7;             // channel group
        if (p0 + p < NPIX) {
            float4 v;
            v.x = tile[4 * g + 0][p];
            v.y = tile[4 * g + 1][p];
            v.z = tile[4 * g + 2][p];
            v.w = tile[4 * g + 3][p];
            *(float4*)(ob + (size_t)(p0 + p) * CH + 4 * g) = v;
        }
    }
}

// ---------------------------------------------------------------------------
// Kernel 2: fused RoIAlign (8x8 grid) + 2x2 avg pool -> (K,C,7,7)
// Grid (K, 2): each block covers 512 channels of one roi. 256 threads,
// 2 channels/thread (float2 taps), 49 float2 register accumulators,
// chunked smem staging + fully-coalesced float4 output stores.
// ---------------------------------------------------------------------------
__global__ __launch_bounds__(256, 2)
void roi_pool_kernel(const float* __restrict__ rois, float* __restrict__ out) {
    const int k     = blockIdx.x;
    const int chunk = blockIdx.y;          // 0 or 1: channel half
    const int tid   = threadIdx.x;

    __shared__ __align__(16) float sbuf[128 * 49];   // 25 KB staging
    __shared__ float s_wx[GPTS], s_wy[GPTS], s_vx[GPTS], s_vy[GPTS];
    __shared__ int   s_x0[GPTS], s_y0[GPTS];
    __shared__ int   s_b;

    if (tid < GPTS) {
        float x1 = __ldg(&rois[k * 5 + 1]) * 0.0625f;
        float y1 = __ldg(&rois[k * 5 + 2]) * 0.0625f;
        float x2 = __ldg(&rois[k * 5 + 3]) * 0.0625f;
        float y2 = __ldg(&rois[k * 5 + 4]) * 0.0625f;
        float bh = fmaxf(y2 - y1, 0.0f) * (1.0f / 7.0f);
        float bw = fmaxf(x2 - x1, 0.0f) * (1.0f / 7.0f);
        float xv = x1 + (float)tid * bw;
        float yv = y1 + (float)tid * bh;
        s_vx[tid] = (xv >= 0.0f && xv < (float)WW) ? 1.0f : 0.0f;
        s_vy[tid] = (yv >= 0.0f && yv < (float)HH) ? 1.0f : 0.0f;
        int x0 = (int)floorf(xv);  x0 = min(max(x0, 0), WW - 2);
        int y0 = (int)floorf(yv);  y0 = min(max(y0, 0), HH - 2);
        s_x0[tid] = x0;  s_y0[tid] = y0;
        s_wx[tid] = xv - (float)x0;
        s_wy[tid] = yv - (float)y0;
        if (tid == 0) s_b = (int)__ldg(&rois[k * 5 + 0]);
    }
    __syncthreads();

    const int c0 = chunk * 512 + tid * 2;            // global channel
    const float* bptr = FT + (size_t)s_b * (NPIX * CH) + c0;

    float2 acc[49];
    #pragma unroll
    for (int i = 0; i < 49; i++) { acc[i].x = 0.0f; acc[i].y = 0.0f; }

    #pragma unroll
    for (int gy = 0; gy < GPTS; gy++) {
        const int   y0 = s_y0[gy];
        const float wy = s_wy[gy];
        const float vy = s_vy[gy];
        const float* rp = bptr + (size_t)y0 * (WW * CH);
        #pragma unroll
        for (int gx = 0; gx < GPTS; gx++) {
            const int   x0 = s_x0[gx];
            const float wx = s_wx[gx];
            const float sc = 0.25f * vy * s_vx[gx];

            const float* p = rp + x0 * CH;
            float2 v00 = *(const float2*)(p);
            float2 v01 = *(const float2*)(p + CH);
            float2 v10 = *(const float2*)(p + WW * CH);
            float2 v11 = *(const float2*)(p + WW * CH + CH);

            float w00 = (1.0f - wy) * (1.0f - wx) * sc;
            float w01 = (1.0f - wy) * wx * sc;
            float w10 = wy * (1.0f - wx) * sc;
            float w11 = wy * wx * sc;

            float ax = v00.x*w00 + v01.x*w01 + v10.x*w10 + v11.x*w11;
            float ay = v00.y*w00 + v01.y*w01 + v10.y*w10 + v11.y*w11;

            if (gy >= 1 && gx >= 1) { acc[(gy-1)*7 + (gx-1)].x += ax; acc[(gy-1)*7 + (gx-1)].y += ay; }
            if (gy >= 1 && gx <  7) { acc[(gy-1)*7 +  gx   ].x += ax; acc[(gy-1)*7 +  gx   ].y += ay; }
            if (gy <  7 && gx >= 1) { acc[ gy   *7 + (gx-1)].x += ax; acc[ gy   *7 + (gx-1)].y += ay; }
            if (gy <  7 && gx <  7) { acc[ gy   *7 +  gx   ].x += ax; acc[ gy   *7 +  gx   ].y += ay; }
        }
    }

    // ---- staged, coalesced output writes -------------------------------
    // This block owns a contiguous run of 512*49 floats. Stage 128 channels
    // (6272 floats) at a time, then drain with float4 stores.
    float* outk = out + (size_t)k * (CH * 49) + (size_t)chunk * (512 * 49);
    #pragma unroll
    for (int sub = 0; sub < 4; sub++) {
        if ((tid >> 6) == sub) {
            int cl = tid * 2 - sub * 128;   // 0..126, even
            #pragma unroll
            for (int i = 0; i < 49; i++) {
                sbuf[(cl    ) * 49 + i] = acc[i].x;
                sbuf[(cl + 1) * 49 + i] = acc[i].y;
            }
        }
        __syncthreads();
        const float4* s4 = (const float4*)sbuf;
        float4* o4 = (float4*)(outk + sub * 6272);
        #pragma unroll
        for (int j = 0; j < 7; j++) {            // 7*256 > 1568
            int i = tid + j * 256;
            if (i < 1568) o4[i] = s4[i];
        }
        __syncthreads();
    }
}

// ---------------------------------------------------------------------------
extern "C" void kernel_launch(void* const* d_in, const int* in_sizes, int n_in,
                              void* d_out, int out_size) {
    const float* features = (const float*)d_in[0];
    const float* rois     = (const float*)d_in[1];
    float* out            = (float*)d_out;

    dim3 tgrid((NPIX + 127) / 128, CH / 32, BB);   // (20, 32, 4)
    transpose_kernel<<<tgrid, 256>>>(features);
    roi_pool_kernel<<<dim3(KK, 2), 256>>>(rois, out);
}